// round 1
// baseline (speedup 1.0000x reference)
#include <cuda_runtime.h>
#include <cuda_bf16.h>
#include <math.h>

// ---------------------------------------------------------------------------
// AFTFull:  Q,K,V = x@W+b ; ew=exp(wbias); num/den = ew @ (eK*V | eK);
//           Yt = sigmoid(Q)*num/den ; out = Yt@Wp + bp
// Shapes: B=4, T=2048, DIM=1024, HID=256  ->  rows = B*T = 8192
// ---------------------------------------------------------------------------

#define ROWS   8192      // B*T
#define DIM_   1024
#define HID_   256
#define TT     2048      // T (== MAXT here)

// scratch (static device globals; allocation-free per harness rules)
__device__ float g_QKV [ROWS * 768];        // [rows][ q(256) | k(256) | v(256) ]
__device__ float g_F   [ROWS * 512];        // [rows][ eK*V(256) | eK(256) ]
__device__ float g_sigQ[ROWS * 256];
__device__ float g_ew  [TT * TT];
__device__ float g_ND  [ROWS * 512];        // [rows][ num(256) | den(256) ]
__device__ float g_Yt  [ROWS * 256];

// ---------------------------------------------------------------------------
// packed f32x2 helpers (Blackwell FFMA2 path — only reachable via PTX)
// ---------------------------------------------------------------------------
__device__ __forceinline__ unsigned long long pack2(float lo, float hi) {
    unsigned long long r;
    asm("mov.b64 %0, {%1, %2};" : "=l"(r) : "f"(lo), "f"(hi));
    return r;
}
__device__ __forceinline__ void ffma2(unsigned long long& c,
                                      unsigned long long a,
                                      unsigned long long b) {
    asm("fma.rn.f32x2 %0, %1, %2, %0;" : "+l"(c) : "l"(a), "l"(b));
}
__device__ __forceinline__ float2 unpack2(unsigned long long v) {
    float2 r;
    asm("mov.b64 {%0, %1}, %2;" : "=f"(r.x), "=f"(r.y) : "l"(v));
    return r;
}

// ---------------------------------------------------------------------------
// tiled SGEMM:  C[M,N] = A[M,K] @ B[K,N] (+ bias[N]), batched via z-strides.
// BM=BN=128, BK=16, 256 threads, 8x8 per thread, FFMA2 microkernel.
// All problem dims here are multiples of the tile sizes -> no bounds checks.
// ---------------------------------------------------------------------------
#define BM 128
#define BN 128
#define BK 16
#define TM 8
#define TN 8

__global__ __launch_bounds__(256, 2)
void sgemm_bias(const float* __restrict__ A, const float* __restrict__ B,
                const float* __restrict__ bias, float* __restrict__ C,
                int K, int lda, int ldb, int ldc,
                long long sA, long long sB, long long sC)
{
    A += (long long)blockIdx.z * sA;
    B += (long long)blockIdx.z * sB;
    C += (long long)blockIdx.z * sC;

    __shared__ __align__(16) float As[BK][BM];   // transposed A tile
    __shared__ __align__(16) float Bs[BK][BN];

    const int tid = threadIdx.x;
    const int tx  = tid & 15;        // 0..15 -> N direction
    const int ty  = tid >> 4;        // 0..15 -> M direction

    const int m0 = blockIdx.y * BM;
    const int n0 = blockIdx.x * BN;

    // global-load mappings
    const int arow = tid >> 2;           // 0..63   (+64 second half)
    const int acol = (tid & 3) * 4;      // 0,4,8,12
    const int brow = tid >> 5;           // 0..7    (+8 second half)
    const int bcol = (tid & 31) * 4;     // 0..124

    unsigned long long acc2[TM][4];
    #pragma unroll
    for (int i = 0; i < TM; ++i)
        #pragma unroll
        for (int j = 0; j < 4; ++j) acc2[i][j] = 0ULL;   // {0.f,0.f}

    for (int k0 = 0; k0 < K; k0 += BK) {
        // load A tile (transposed into As[k][m])
        #pragma unroll
        for (int r = 0; r < 2; ++r) {
            int mrow = arow + r * 64;
            float4 v = *(const float4*)(A + (long long)(m0 + mrow) * lda + k0 + acol);
            As[acol + 0][mrow] = v.x;
            As[acol + 1][mrow] = v.y;
            As[acol + 2][mrow] = v.z;
            As[acol + 3][mrow] = v.w;
        }
        // load B tile
        #pragma unroll
        for (int r = 0; r < 2; ++r) {
            int krow = brow + r * 8;
            float4 v = *(const float4*)(B + (long long)(k0 + krow) * ldb + n0 + bcol);
            *(float4*)&Bs[krow][bcol] = v;
        }
        __syncthreads();

        #pragma unroll
        for (int kk = 0; kk < BK; ++kk) {
            float4 a0 = *(const float4*)&As[kk][ty * TM];
            float4 a1 = *(const float4*)&As[kk][ty * TM + 4];
            ulonglong2 bl0 = *(const ulonglong2*)&Bs[kk][tx * TN];
            ulonglong2 bl1 = *(const ulonglong2*)&Bs[kk][tx * TN + 4];
            unsigned long long bb[4] = { bl0.x, bl0.y, bl1.x, bl1.y };
            float av[8] = { a0.x, a0.y, a0.z, a0.w, a1.x, a1.y, a1.z, a1.w };
            #pragma unroll
            for (int i = 0; i < TM; ++i) {
                unsigned long long aa = pack2(av[i], av[i]);
                #pragma unroll
                for (int j = 0; j < 4; ++j) ffma2(acc2[i][j], aa, bb[j]);
            }
        }
        __syncthreads();
    }

    // epilogue
    float bfr[TN];
    #pragma unroll
    for (int j = 0; j < TN; ++j)
        bfr[j] = bias ? bias[n0 + tx * TN + j] : 0.0f;

    #pragma unroll
    for (int i = 0; i < TM; ++i) {
        long long row = m0 + ty * TM + i;
        float o[8];
        #pragma unroll
        for (int j = 0; j < 4; ++j) {
            float2 p = unpack2(acc2[i][j]);
            o[2 * j]     = p.x + bfr[2 * j];
            o[2 * j + 1] = p.y + bfr[2 * j + 1];
        }
        float* cp = C + row * ldc + n0 + tx * TN;
        *(float4*)(cp)     = make_float4(o[0], o[1], o[2], o[3]);
        *(float4*)(cp + 4) = make_float4(o[4], o[5], o[6], o[7]);
    }
}

// ---------------------------------------------------------------------------
// elementwise kernels
// ---------------------------------------------------------------------------
__global__ void exp_k(const float* __restrict__ in, float* __restrict__ out, int n)
{
    int i = blockIdx.x * blockDim.x + threadIdx.x;
    if (i < n) out[i] = expf(in[i]);
}

__global__ void qkv_post(const float* __restrict__ QKV,
                         float* __restrict__ sigQ, float* __restrict__ F)
{
    int i = blockIdx.x * blockDim.x + threadIdx.x;          // 0 .. ROWS*256
    int row = i >> 8, h = i & 255;
    const float* base = QKV + (long long)row * 768;
    float q = base[h];
    float k = base[256 + h];
    float v = base[512 + h];
    sigQ[i] = 1.0f / (1.0f + expf(-q));
    float ek = expf(k);
    long long fo = (long long)row * 512 + h;
    F[fo]       = ek * v;
    F[fo + 256] = ek;
}

__global__ void attn_post(const float* __restrict__ sigQ,
                          const float* __restrict__ ND,
                          float* __restrict__ Yt)
{
    int i = blockIdx.x * blockDim.x + threadIdx.x;          // 0 .. ROWS*256
    int row = i >> 8, h = i & 255;
    long long o = (long long)row * 512 + h;
    Yt[i] = sigQ[i] * (ND[o] / ND[o + 256]);
}

// ---------------------------------------------------------------------------
// launch
// ---------------------------------------------------------------------------
extern "C" void kernel_launch(void* const* d_in, const int* in_sizes, int n_in,
                              void* d_out, int out_size)
{
    const float* x     = (const float*)d_in[0];
    const float* Wq    = (const float*)d_in[1];
    const float* bq    = (const float*)d_in[2];
    const float* Wk    = (const float*)d_in[3];
    const float* bk    = (const float*)d_in[4];
    const float* Wv    = (const float*)d_in[5];
    const float* bv    = (const float*)d_in[6];
    const float* Wp    = (const float*)d_in[7];
    const float* bp    = (const float*)d_in[8];
    const float* wbias = (const float*)d_in[9];
    float* out = (float*)d_out;

    float *pQKV, *pF, *psigQ, *pew, *pND, *pYt;
    cudaGetSymbolAddress((void**)&pQKV,  g_QKV);
    cudaGetSymbolAddress((void**)&pF,    g_F);
    cudaGetSymbolAddress((void**)&psigQ, g_sigQ);
    cudaGetSymbolAddress((void**)&pew,   g_ew);
    cudaGetSymbolAddress((void**)&pND,   g_ND);
    cudaGetSymbolAddress((void**)&pYt,   g_Yt);

    // 1) QKV projections: x[8192,1024] @ W[1024,256] -> columns of g_QKV[8192,768]
    dim3 gQKV(HID_ / BN, ROWS / BM, 1);   // (2,64)
    sgemm_bias<<<gQKV, 256>>>(x, Wq, bq, pQKV + 0,   DIM_, DIM_, HID_, 768, 0, 0, 0);
    sgemm_bias<<<gQKV, 256>>>(x, Wk, bk, pQKV + 256, DIM_, DIM_, HID_, 768, 0, 0, 0);
    sgemm_bias<<<gQKV, 256>>>(x, Wv, bv, pQKV + 512, DIM_, DIM_, HID_, 768, 0, 0, 0);

    // 2) ew = exp(wbias)   (T == MAXT, so the full matrix)
    exp_k<<<(TT * TT) / 256, 256>>>(wbias, pew, TT * TT);

    // 3) sigQ / F = [eK*V | eK]
    qkv_post<<<(ROWS * 256) / 256, 256>>>(pQKV, psigQ, pF);

    // 4) batched attention GEMM: ND[b] = ew @ F[b]   (M=2048,N=512,K=2048, batch 4)
    dim3 gATT(512 / BN, TT / BM, 4);      // (4,16,4)
    sgemm_bias<<<gATT, 256>>>(pew, pF, nullptr, pND,
                              TT, TT, 512, 512,
                              0LL, (long long)TT * 512, (long long)TT * 512);

    // 5) Yt = sigmoid(Q) * num / den
    attn_post<<<(ROWS * 256) / 256, 256>>>(psigQ, pND, pYt);

    // 6) out = Yt @ Wp + bp : [8192,256] @ [256,1024]
    dim3 gOUT(DIM_ / BN, ROWS / BM, 1);   // (8,64)
    sgemm_bias<<<gOUT, 256>>>(pYt, Wp, bp, out, HID_, HID_, DIM_, DIM_, 0, 0, 0);
}

// round 3
// speedup vs baseline: 2.8916x; 2.8916x over previous
#include <cuda_runtime.h>
#include <cuda_bf16.h>
#include <math.h>
#include <stdint.h>

// ---------------------------------------------------------------------------
// AFTFull via warp-level mma.sync (HMMA bf16, fp32 accum), split precision.
//   QKV = x @ [Wq|Wk|Wv] + b          (M=8192, N=768,  K=1024)
//   ND  = exp(wbias) @ [eK*V | eK]^T  (M=2048, N=512,  K=2048, batch=4)
//   out = (sig(Q)*num/den) @ Wp + bp  (M=8192, N=1024, K=256)
// fp32 -> bf16 hi+lo split; each GEMM accumulates hi*hi + hi*lo + lo*hi.
// (tcgen05 is unavailable: harness PTX stage targets compute_103 baseline.)
// ---------------------------------------------------------------------------

#define ROWS 8192
#define DIM_ 1024
#define HID_ 256
#define TT   2048

// ------------------------------- scratch -----------------------------------
__device__ __nv_bfloat16 g_xhi [ROWS * DIM_], g_xlo [ROWS * DIM_];
__device__ __nv_bfloat16 g_wqkv_hi[768 * DIM_], g_wqkv_lo[768 * DIM_];
__device__ float         g_bqkv[768];
__device__ __nv_bfloat16 g_ewhi[TT * TT], g_ewlo[TT * TT];
__device__ float         g_QKV [ROWS * 768];
__device__ float         g_sigQ[ROWS * HID_];
__device__ __nv_bfloat16 g_fthi[4 * 512 * TT], g_ftlo[4 * 512 * TT];   // [b][n][s]
__device__ float         g_ND  [ROWS * 512];
__device__ __nv_bfloat16 g_ythi[ROWS * HID_], g_ytlo[ROWS * HID_];
__device__ __nv_bfloat16 g_wpt_hi[DIM_ * HID_], g_wpt_lo[DIM_ * HID_]; // [d][h]

// ----------------------------- PTX helpers ---------------------------------
__device__ __forceinline__ uint32_t s2u(const void* p) {
    uint32_t a;
    asm("{ .reg .u64 t; cvta.to.shared.u64 t, %1; cvt.u32.u64 %0, t; }"
        : "=r"(a) : "l"(p));
    return a;
}
__device__ __forceinline__ void cp16(uint32_t saddr, const void* g) {
    asm volatile("cp.async.cg.shared.global [%0], [%1], 16;"
                 :: "r"(saddr), "l"(g) : "memory");
}
#define CP_COMMIT() asm volatile("cp.async.commit_group;" ::: "memory")
#define CP_WAIT1()  asm volatile("cp.async.wait_group 1;"  ::: "memory")

__device__ __forceinline__ void ldsm_x4(uint32_t* r, uint32_t addr) {
    asm volatile("ldmatrix.sync.aligned.m8n8.x4.shared.b16 {%0,%1,%2,%3}, [%4];"
                 : "=r"(r[0]), "=r"(r[1]), "=r"(r[2]), "=r"(r[3]) : "r"(addr));
}
__device__ __forceinline__ void ldsm_x2(uint32_t* r, uint32_t addr) {
    asm volatile("ldmatrix.sync.aligned.m8n8.x2.shared.b16 {%0,%1}, [%2];"
                 : "=r"(r[0]), "=r"(r[1]) : "r"(addr));
}
__device__ __forceinline__ void mma16816(float* d, const uint32_t* a, const uint32_t* b) {
    asm volatile("mma.sync.aligned.m16n8k16.row.col.f32.bf16.bf16.f32 "
                 "{%0,%1,%2,%3}, {%4,%5,%6,%7}, {%8,%9}, {%0,%1,%2,%3};"
                 : "+f"(d[0]), "+f"(d[1]), "+f"(d[2]), "+f"(d[3])
                 : "r"(a[0]), "r"(a[1]), "r"(a[2]), "r"(a[3]), "r"(b[0]), "r"(b[1]));
}

// ------------------------------ HMMA GEMM ----------------------------------
// C[M,N] fp32 = A@B^T (+bias).  A: (Ahi,Alo)[M,K] K-major bf16.
// B: (Bhi,Blo)[N,K] K-major bf16.  CTA tile 128x128, BK=64, 256 threads,
// 8 warps as 2(M) x 4(N) -> 64x32 warp tiles. cp.async double buffer.
#define GEMM_SMEM (2 * 4 * 16384)       // 2 stages * 4 tiles(Ahi,Alo,Bhi,Blo) * 16KB
#define STAGE_STRIDE 65536

__device__ __forceinline__ void load_stage(
    uint32_t sbase, int tid,
    const __nv_bfloat16* Ahi, const __nv_bfloat16* Alo,
    const __nv_bfloat16* Bhi, const __nv_bfloat16* Blo,
    int lda, int ldb, int k0)
{
    #pragma unroll
    for (int t = 0; t < 16; ++t) {
        const int i = tid + t * 256;
        const int tile = i >> 10;          // 0..3
        const int w = i & 1023;
        const int row = w >> 3;            // 0..127
        const int c = w & 7;               // 16B chunk within 128B row
        const __nv_bfloat16* base =
            (tile == 0) ? Ahi : (tile == 1) ? Alo : (tile == 2) ? Bhi : Blo;
        const int ld = (tile < 2) ? lda : ldb;
        const __nv_bfloat16* src = base + (long long)row * ld + k0 + c * 8;
        const uint32_t dst = sbase + tile * 16384 + row * 128 + ((c ^ (row & 7)) * 16);
        cp16(dst, src);
    }
}

__global__ __launch_bounds__(256, 1)
void mma_gemm(const __nv_bfloat16* __restrict__ Ahi, const __nv_bfloat16* __restrict__ Alo,
              const __nv_bfloat16* __restrict__ Bhi, const __nv_bfloat16* __restrict__ Blo,
              const float* __restrict__ bias, float* __restrict__ C,
              int K, int lda, int ldb, int ldc,
              long long sA, long long sB, long long sC)
{
    extern __shared__ char smem[];
    const uint32_t sb = s2u(smem);
    const int tid  = threadIdx.x;
    const int wid  = tid >> 5;
    const int lane = tid & 31;

    Ahi += (long long)blockIdx.z * sA;  Alo += (long long)blockIdx.z * sA;
    Bhi += (long long)blockIdx.z * sB;  Blo += (long long)blockIdx.z * sB;
    C   += (long long)blockIdx.z * sC;

    const int m0 = blockIdx.y * 128;
    const int n0 = blockIdx.x * 128;
    const __nv_bfloat16* tAhi = Ahi + (long long)m0 * lda;
    const __nv_bfloat16* tAlo = Alo + (long long)m0 * lda;
    const __nv_bfloat16* tBhi = Bhi + (long long)n0 * ldb;
    const __nv_bfloat16* tBlo = Blo + (long long)n0 * ldb;

    const int wm = (wid >> 2) * 64;        // warp M offset within tile
    const int wn = (wid & 3) * 32;         // warp N offset within tile

    const int kc = K / 64;

    float acc[4][4][4];
    #pragma unroll
    for (int i = 0; i < 4; ++i)
        #pragma unroll
        for (int j = 0; j < 4; ++j)
            #pragma unroll
            for (int q = 0; q < 4; ++q) acc[i][j][q] = 0.f;

    // prologue: stage 0 and 1
    load_stage(sb,                tid, tAhi, tAlo, tBhi, tBlo, lda, ldb, 0);
    CP_COMMIT();
    if (kc > 1) load_stage(sb + STAGE_STRIDE, tid, tAhi, tAlo, tBhi, tBlo, lda, ldb, 64);
    CP_COMMIT();

    // per-thread ldmatrix row bits (constant across k)
    const int rA  = (lane & 15);           // A: row within m16 tile
    const int cA  = (lane >> 4);           // A: k 16B-chunk select (0/1)
    const int rB  = (lane & 7);            // B: row within n8 tile
    const int cB  = (lane >> 3) & 1;       // B: k 16B-chunk select (0/1)

    for (int k = 0; k < kc; ++k) {
        CP_WAIT1();
        __syncthreads();

        const uint32_t st = sb + (k & 1) * STAGE_STRIDE;
        const uint32_t aHiB = st;
        const uint32_t aLoB = st + 16384;
        const uint32_t bHiB = st + 32768;
        const uint32_t bLoB = st + 49152;

        #pragma unroll
        for (int kk = 0; kk < 4; ++kk) {
            uint32_t ah[4][4], al[4][4], bh[4][2], bl[4][2];
            #pragma unroll
            for (int i = 0; i < 4; ++i) {
                const int row = wm + i * 16 + rA;
                const uint32_t off = row * 128 + (((kk * 2 + cA) ^ (row & 7)) * 16);
                ldsm_x4(ah[i], aHiB + off);
                ldsm_x4(al[i], aLoB + off);
            }
            #pragma unroll
            for (int j = 0; j < 4; ++j) {
                const int row = wn + j * 8 + rB;
                const uint32_t off = row * 128 + (((kk * 2 + cB) ^ (row & 7)) * 16);
                ldsm_x2(bh[j], bHiB + off);
                ldsm_x2(bl[j], bLoB + off);
            }
            #pragma unroll
            for (int i = 0; i < 4; ++i)
                #pragma unroll
                for (int j = 0; j < 4; ++j) {
                    mma16816(acc[i][j], ah[i], bh[j]);
                    mma16816(acc[i][j], ah[i], bl[j]);
                    mma16816(acc[i][j], al[i], bh[j]);
                }
        }
        __syncthreads();

        if (k + 2 < kc)
            load_stage(sb + (k & 1) * STAGE_STRIDE, tid,
                       tAhi, tAlo, tBhi, tBlo, lda, ldb, (k + 2) * 64);
        CP_COMMIT();
    }

    // ------------------------------ epilogue --------------------------------
    const int g  = lane >> 2;
    const int tg = lane & 3;
    #pragma unroll
    for (int j = 0; j < 4; ++j) {
        const int n = n0 + wn + j * 8 + tg * 2;
        const float b0 = bias ? bias[n]     : 0.f;
        const float b1 = bias ? bias[n + 1] : 0.f;
        #pragma unroll
        for (int i = 0; i < 4; ++i) {
            const long long m = m0 + wm + i * 16 + g;
            *(float2*)(C + m * ldc + n) =
                make_float2(acc[i][j][0] + b0, acc[i][j][1] + b1);
            *(float2*)(C + (m + 8) * ldc + n) =
                make_float2(acc[i][j][2] + b0, acc[i][j][3] + b1);
        }
    }
}

// --------------------------- conversion kernels ----------------------------
__device__ __forceinline__ void split2(float v, __nv_bfloat16* h, __nv_bfloat16* l) {
    __nv_bfloat16 hh = __float2bfloat16_rn(v);
    *h = hh;
    *l = __float2bfloat16_rn(v - __bfloat162float(hh));
}

__global__ void cvt_split(const float* __restrict__ in,
                          __nv_bfloat16* __restrict__ hi, __nv_bfloat16* __restrict__ lo,
                          int n)
{
    int i = blockIdx.x * blockDim.x + threadIdx.x;
    if (i < n) split2(in[i], hi + i, lo + i);
}

__global__ void cvt_exp_split(const float* __restrict__ in,
                              __nv_bfloat16* __restrict__ hi, __nv_bfloat16* __restrict__ lo,
                              int n)
{
    int i = blockIdx.x * blockDim.x + threadIdx.x;
    if (i < n) split2(expf(in[i]), hi + i, lo + i);
}

__global__ void build_wqkv(const float* __restrict__ Wq, const float* __restrict__ Wk,
                           const float* __restrict__ Wv,
                           const float* __restrict__ bq, const float* __restrict__ bk,
                           const float* __restrict__ bv,
                           __nv_bfloat16* __restrict__ hi, __nv_bfloat16* __restrict__ lo,
                           float* __restrict__ bcat)
{
    int i = blockIdx.x * blockDim.x + threadIdx.x;     // 768*1024
    if (i >= 768 * DIM_) return;
    int n = i / DIM_, k = i % DIM_;
    const float* W = (n < 256) ? Wq : (n < 512) ? Wk : Wv;
    split2(W[(long long)k * 256 + (n & 255)], hi + i, lo + i);
    if (i < 768) {
        const float* b = (i < 256) ? bq : (i < 512) ? bk : bv;
        bcat[i] = b[i & 255];
    }
}

__global__ void build_wpt(const float* __restrict__ Wp,
                          __nv_bfloat16* __restrict__ hi, __nv_bfloat16* __restrict__ lo)
{
    int i = blockIdx.x * blockDim.x + threadIdx.x;     // 1024*256
    if (i >= DIM_ * HID_) return;
    int d = i >> 8, h = i & 255;
    split2(Wp[(long long)h * DIM_ + d], hi + i, lo + i);
}

// sigQ + transposed F = [eK*V ; eK] (hi/lo), via 32x32 smem transpose
__global__ void qkv_post(const float* __restrict__ QKV, float* __restrict__ sigQ,
                         __nv_bfloat16* __restrict__ fthi, __nv_bfloat16* __restrict__ ftlo)
{
    __shared__ float tkv[32][33], tk[32][33];
    const int b = blockIdx.z, s0 = blockIdx.y * 32, h0 = blockIdx.x * 32;
    const int tx = threadIdx.x, ty = threadIdx.y;
    #pragma unroll
    for (int r = 0; r < 4; ++r) {
        const int s = s0 + ty + r * 8;
        const float* base = QKV + ((long long)(b * 2048 + s)) * 768;
        float q  = base[h0 + tx];
        float kk = base[256 + h0 + tx];
        float v  = base[512 + h0 + tx];
        sigQ[((long long)(b * 2048 + s)) * 256 + h0 + tx] = 1.f / (1.f + expf(-q));
        float ek = expf(kk);
        tkv[ty + r * 8][tx] = ek * v;
        tk [ty + r * 8][tx] = ek;
    }
    __syncthreads();
    #pragma unroll
    for (int r = 0; r < 4; ++r) {
        const int h = h0 + ty + r * 8;
        float v1 = tkv[tx][ty + r * 8];
        float v2 = tk [tx][ty + r * 8];
        long long o1 = ((long long)b * 512 + h) * 2048 + s0 + tx;
        long long o2 = ((long long)b * 512 + 256 + h) * 2048 + s0 + tx;
        split2(v1, fthi + o1, ftlo + o1);
        split2(v2, fthi + o2, ftlo + o2);
    }
}

__global__ void attn_post(const float* __restrict__ sigQ, const float* __restrict__ ND,
                          __nv_bfloat16* __restrict__ ythi, __nv_bfloat16* __restrict__ ytlo)
{
    int i = blockIdx.x * blockDim.x + threadIdx.x;     // ROWS*256
    if (i >= ROWS * HID_) return;
    int row = i >> 8, h = i & 255;
    long long o = (long long)row * 512 + h;
    float y = sigQ[i] * (ND[o] / ND[o + 256]);
    split2(y, ythi + i, ytlo + i);
}

// -------------------------------- launch ------------------------------------
extern "C" void kernel_launch(void* const* d_in, const int* in_sizes, int n_in,
                              void* d_out, int out_size)
{
    const float* x     = (const float*)d_in[0];
    const float* Wq    = (const float*)d_in[1];
    const float* bq    = (const float*)d_in[2];
    const float* Wk    = (const float*)d_in[3];
    const float* bk    = (const float*)d_in[4];
    const float* Wv    = (const float*)d_in[5];
    const float* bv    = (const float*)d_in[6];
    const float* Wp    = (const float*)d_in[7];
    const float* bp    = (const float*)d_in[8];
    const float* wbias = (const float*)d_in[9];
    float* out = (float*)d_out;

    __nv_bfloat16 *pxhi, *pxlo, *pwqh, *pwql, *pewh, *pewl, *pfth, *pftl,
                  *pyth, *pytl, *pwph, *pwpl;
    float *pbq, *pQKV, *psigQ, *pND;
    cudaGetSymbolAddress((void**)&pxhi, g_xhi);      cudaGetSymbolAddress((void**)&pxlo, g_xlo);
    cudaGetSymbolAddress((void**)&pwqh, g_wqkv_hi);  cudaGetSymbolAddress((void**)&pwql, g_wqkv_lo);
    cudaGetSymbolAddress((void**)&pbq,  g_bqkv);
    cudaGetSymbolAddress((void**)&pewh, g_ewhi);     cudaGetSymbolAddress((void**)&pewl, g_ewlo);
    cudaGetSymbolAddress((void**)&pQKV, g_QKV);
    cudaGetSymbolAddress((void**)&psigQ, g_sigQ);
    cudaGetSymbolAddress((void**)&pfth, g_fthi);     cudaGetSymbolAddress((void**)&pftl, g_ftlo);
    cudaGetSymbolAddress((void**)&pND,  g_ND);
    cudaGetSymbolAddress((void**)&pyth, g_ythi);     cudaGetSymbolAddress((void**)&pytl, g_ytlo);
    cudaGetSymbolAddress((void**)&pwph, g_wpt_hi);   cudaGetSymbolAddress((void**)&pwpl, g_wpt_lo);

    cudaFuncSetAttribute(mma_gemm, cudaFuncAttributeMaxDynamicSharedMemorySize, GEMM_SMEM);

    // conversions
    cvt_split<<<(ROWS * DIM_ + 255) / 256, 256>>>(x, pxhi, pxlo, ROWS * DIM_);
    build_wqkv<<<(768 * DIM_ + 255) / 256, 256>>>(Wq, Wk, Wv, bq, bk, bv, pwqh, pwql, pbq);
    cvt_exp_split<<<(TT * TT + 255) / 256, 256>>>(wbias, pewh, pewl, TT * TT);
    build_wpt<<<(DIM_ * HID_ + 255) / 256, 256>>>(Wp, pwph, pwpl);

    // GEMM 1: QKV = x @ Wqkv + b     [8192 x 768 x 1024]
    dim3 g1(768 / 128, ROWS / 128, 1);
    mma_gemm<<<g1, 256, GEMM_SMEM>>>(pxhi, pxlo, pwqh, pwql, pbq, pQKV,
                                     DIM_, DIM_, DIM_, 768, 0, 0, 0);

    // sigQ + transposed F
    dim3 bq1(32, 8), gq1(HID_ / 32, TT / 32, 4);
    qkv_post<<<gq1, bq1>>>(pQKV, psigQ, pfth, pftl);

    // GEMM 2: ND[b] = ew @ F[b]^T    [2048 x 512 x 2048] x 4
    dim3 g2(512 / 128, TT / 128, 4);
    mma_gemm<<<g2, 256, GEMM_SMEM>>>(pewh, pewl, pfth, pftl, nullptr, pND,
                                     TT, TT, TT, 512,
                                     0LL, (long long)512 * TT, (long long)TT * 512);

    // Yt
    attn_post<<<(ROWS * HID_ + 255) / 256, 256>>>(psigQ, pND, pyth, pytl);

    // GEMM 3: out = Yt @ Wp + bp     [8192 x 1024 x 256]
    dim3 g3(DIM_ / 128, ROWS / 128, 1);
    mma_gemm<<<g3, 256, GEMM_SMEM>>>(pyth, pytl, pwph, pwpl, bp, out,
                                     HID_, HID_, HID_, DIM_, 0, 0, 0);
}

// round 4
// speedup vs baseline: 3.6119x; 1.2491x over previous
#include <cuda_runtime.h>
#include <cuda_bf16.h>
#include <math.h>
#include <stdint.h>

// ---------------------------------------------------------------------------
// AFTFull via warp-level mma.sync (HMMA bf16, fp32 accum).
//   GEMM1: QKV = x @ [Wq|Wk|Wv] + b     split 3-pass   (8192 x 768 x 1024)
//   GEMM2: ew = 1 + R, |R|<=0.039  ->   ND = colsum(F) + R@F, single pass
//          (2048 x 512 x 2048) x4, epilogue fused: Yt = sig(Q)*num/den
//   GEMM3: out = Yt @ Wp + bp           split 3-pass   (8192 x 1024 x 256)
// ---------------------------------------------------------------------------

#define ROWS 8192
#define DIM_ 1024
#define HID_ 256
#define TT   2048

// ------------------------------- scratch -----------------------------------
__device__ __nv_bfloat16 g_xhi [ROWS * DIM_], g_xlo [ROWS * DIM_];
__device__ __nv_bfloat16 g_wqkv_hi[768 * DIM_], g_wqkv_lo[768 * DIM_];
__device__ float         g_bqkv[768];
__device__ __nv_bfloat16 g_R   [TT * TT];                 // exp(wbias)-1
__device__ float         g_QKV [ROWS * 768];
__device__ float         g_sigQ[ROWS * HID_];
__device__ __nv_bfloat16 g_F   [4 * 512 * TT];            // [b][2h|2h+1][s]
__device__ float         g_cspart[4 * 64 * 512];          // [b][sblk][n]
__device__ float         g_cs  [4 * 512];                 // [b][n] colsums
__device__ __nv_bfloat16 g_ythi[ROWS * HID_], g_ytlo[ROWS * HID_];
__device__ __nv_bfloat16 g_wpt_hi[DIM_ * HID_], g_wpt_lo[DIM_ * HID_];

// ----------------------------- PTX helpers ---------------------------------
__device__ __forceinline__ uint32_t s2u(const void* p) {
    uint32_t a;
    asm("{ .reg .u64 t; cvta.to.shared.u64 t, %1; cvt.u32.u64 %0, t; }"
        : "=r"(a) : "l"(p));
    return a;
}
__device__ __forceinline__ void cp16(uint32_t saddr, const void* g) {
    asm volatile("cp.async.cg.shared.global [%0], [%1], 16;"
                 :: "r"(saddr), "l"(g) : "memory");
}
#define CP_COMMIT() asm volatile("cp.async.commit_group;" ::: "memory")
#define CP_WAIT1()  asm volatile("cp.async.wait_group 1;"  ::: "memory")
#define CP_WAIT2()  asm volatile("cp.async.wait_group 2;"  ::: "memory")

__device__ __forceinline__ void ldsm_x4(uint32_t* r, uint32_t addr) {
    asm volatile("ldmatrix.sync.aligned.m8n8.x4.shared.b16 {%0,%1,%2,%3}, [%4];"
                 : "=r"(r[0]), "=r"(r[1]), "=r"(r[2]), "=r"(r[3]) : "r"(addr));
}
__device__ __forceinline__ void ldsm_x2(uint32_t* r, uint32_t addr) {
    asm volatile("ldmatrix.sync.aligned.m8n8.x2.shared.b16 {%0,%1}, [%2];"
                 : "=r"(r[0]), "=r"(r[1]) : "r"(addr));
}
__device__ __forceinline__ void mma16816(float* d, const uint32_t* a, const uint32_t* b) {
    asm volatile("mma.sync.aligned.m16n8k16.row.col.f32.bf16.bf16.f32 "
                 "{%0,%1,%2,%3}, {%4,%5,%6,%7}, {%8,%9}, {%0,%1,%2,%3};"
                 : "+f"(d[0]), "+f"(d[1]), "+f"(d[2]), "+f"(d[3])
                 : "r"(a[0]), "r"(a[1]), "r"(a[2]), "r"(a[3]), "r"(b[0]), "r"(b[1]));
}

__device__ __forceinline__ void split2(float v, __nv_bfloat16* h, __nv_bfloat16* l) {
    __nv_bfloat16 hh = __float2bfloat16_rn(v);
    *h = hh;
    *l = __float2bfloat16_rn(v - __bfloat162float(hh));
}

// ===================== split-precision GEMM (3-pass) ========================
// C = A@B^T + bias.  A:(Ahi,Alo)[M,K], B:(Bhi,Blo)[N,K], all K-major bf16.
// CTA 128x128, BK=64, 256 thr, 8 warps 2x4 (64x32 warp tiles), 3-stage cp.async.
#define SPLIT_STAGE 65536                 // 4 tiles * 16KB
#define SPLIT_SMEM  (3 * SPLIT_STAGE)

__device__ __forceinline__ void load_stage4(
    uint32_t sbase, int tid,
    const __nv_bfloat16* Ahi, const __nv_bfloat16* Alo,
    const __nv_bfloat16* Bhi, const __nv_bfloat16* Blo,
    int lda, int ldb, int k0)
{
    #pragma unroll
    for (int t = 0; t < 16; ++t) {
        const int i = tid + t * 256;
        const int tile = i >> 10;
        const int w = i & 1023;
        const int row = w >> 3;
        const int c = w & 7;
        const __nv_bfloat16* base =
            (tile == 0) ? Ahi : (tile == 1) ? Alo : (tile == 2) ? Bhi : Blo;
        const int ld = (tile < 2) ? lda : ldb;
        cp16(sbase + tile * 16384 + row * 128 + ((c ^ (row & 7)) * 16),
             base + (long long)row * ld + k0 + c * 8);
    }
}

__global__ __launch_bounds__(256, 1)
void gemm_split(const __nv_bfloat16* __restrict__ Ahi, const __nv_bfloat16* __restrict__ Alo,
                const __nv_bfloat16* __restrict__ Bhi, const __nv_bfloat16* __restrict__ Blo,
                const float* __restrict__ bias, float* __restrict__ C,
                int K, int lda, int ldb, int ldc)
{
    extern __shared__ char smem[];
    const uint32_t sb = s2u(smem);
    const int tid  = threadIdx.x;
    const int wid  = tid >> 5;
    const int lane = tid & 31;

    const int m0 = blockIdx.y * 128;
    const int n0 = blockIdx.x * 128;
    const __nv_bfloat16* tAhi = Ahi + (long long)m0 * lda;
    const __nv_bfloat16* tAlo = Alo + (long long)m0 * lda;
    const __nv_bfloat16* tBhi = Bhi + (long long)n0 * ldb;
    const __nv_bfloat16* tBlo = Blo + (long long)n0 * ldb;

    const int wm = (wid >> 2) * 64;
    const int wn = (wid & 3) * 32;
    const int kc = K / 64;

    float acc[4][4][4];
    #pragma unroll
    for (int i = 0; i < 4; ++i)
        #pragma unroll
        for (int j = 0; j < 4; ++j)
            #pragma unroll
            for (int q = 0; q < 4; ++q) acc[i][j][q] = 0.f;

    load_stage4(sb, tid, tAhi, tAlo, tBhi, tBlo, lda, ldb, 0);
    CP_COMMIT();
    if (kc > 1) load_stage4(sb + SPLIT_STAGE, tid, tAhi, tAlo, tBhi, tBlo, lda, ldb, 64);
    CP_COMMIT();

    const int rA = (lane & 15);
    const int cA = (lane >> 4);
    const int rB = (lane & 7);
    const int cB = (lane >> 3) & 1;

    int stc = 0, stl = 2;                 // compute stage, load stage (mod 3)
    for (int k = 0; k < kc; ++k) {
        CP_WAIT1();
        __syncthreads();

        if (k + 2 < kc)
            load_stage4(sb + stl * SPLIT_STAGE, tid,
                        tAhi, tAlo, tBhi, tBlo, lda, ldb, (k + 2) * 64);
        CP_COMMIT();
        stl = (stl == 2) ? 0 : stl + 1;

        const uint32_t st = sb + stc * SPLIT_STAGE;
        stc = (stc == 2) ? 0 : stc + 1;
        const uint32_t aHiB = st, aLoB = st + 16384;
        const uint32_t bHiB = st + 32768, bLoB = st + 49152;

        #pragma unroll
        for (int kk = 0; kk < 4; ++kk) {
            uint32_t ah[4][4], al[4][4], bh[4][2], bl[4][2];
            #pragma unroll
            for (int i = 0; i < 4; ++i) {
                const int row = wm + i * 16 + rA;
                const uint32_t off = row * 128 + (((kk * 2 + cA) ^ (row & 7)) * 16);
                ldsm_x4(ah[i], aHiB + off);
                ldsm_x4(al[i], aLoB + off);
            }
            #pragma unroll
            for (int j = 0; j < 4; ++j) {
                const int row = wn + j * 8 + rB;
                const uint32_t off = row * 128 + (((kk * 2 + cB) ^ (row & 7)) * 16);
                ldsm_x2(bh[j], bHiB + off);
                ldsm_x2(bl[j], bLoB + off);
            }
            #pragma unroll
            for (int i = 0; i < 4; ++i)
                #pragma unroll
                for (int j = 0; j < 4; ++j) {
                    mma16816(acc[i][j], ah[i], bh[j]);
                    mma16816(acc[i][j], ah[i], bl[j]);
                    mma16816(acc[i][j], al[i], bh[j]);
                }
        }
        __syncthreads();
    }

    const int g  = lane >> 2;
    const int tg = lane & 3;
    #pragma unroll
    for (int j = 0; j < 4; ++j) {
        const int n = n0 + wn + j * 8 + tg * 2;
        const float b0 = bias ? bias[n]     : 0.f;
        const float b1 = bias ? bias[n + 1] : 0.f;
        #pragma unroll
        for (int i = 0; i < 4; ++i) {
            const long long m = m0 + wm + i * 16 + g;
            *(float2*)(C + m * ldc + n) =
                make_float2(acc[i][j][0] + b0, acc[i][j][1] + b1);
            *(float2*)(C + (m + 8) * ldc + n) =
                make_float2(acc[i][j][2] + b0, acc[i][j][3] + b1);
        }
    }
}

// ================= single-pass AFT GEMM with fused epilogue =================
// acc = R[2048,2048] @ F[b][512,2048]^T, then per (t, 2h|2h+1) pair:
//   y = sigQ * (acc0 + cs_num) / (acc1 + cs_den) -> split bf16 Yt.
#define AFT_STAGE 32768                  // 2 tiles * 16KB
#define AFT_SMEM  (4 * AFT_STAGE)

__device__ __forceinline__ void load_stage2(
    uint32_t sbase, int tid,
    const __nv_bfloat16* A, const __nv_bfloat16* B, int lda, int ldb, int k0)
{
    #pragma unroll
    for (int t = 0; t < 8; ++t) {
        const int i = tid + t * 256;
        const int tile = i >> 10;
        const int w = i & 1023;
        const int row = w >> 3;
        const int c = w & 7;
        const __nv_bfloat16* base = tile ? B : A;
        const int ld = tile ? ldb : lda;
        cp16(sbase + tile * 16384 + row * 128 + ((c ^ (row & 7)) * 16),
             base + (long long)row * ld + k0 + c * 8);
    }
}

__global__ __launch_bounds__(256, 1)
void gemm_aft(const __nv_bfloat16* __restrict__ R, const __nv_bfloat16* __restrict__ F,
              const float* __restrict__ cs, const float* __restrict__ sigQ,
              __nv_bfloat16* __restrict__ ythi, __nv_bfloat16* __restrict__ ytlo)
{
    extern __shared__ char smem[];
    const uint32_t sb = s2u(smem);
    const int tid  = threadIdx.x;
    const int wid  = tid >> 5;
    const int lane = tid & 31;
    const int b    = blockIdx.z;

    const int m0 = blockIdx.y * 128;
    const int n0 = blockIdx.x * 128;
    const __nv_bfloat16* tA = R + (long long)m0 * TT;
    const __nv_bfloat16* tB = F + (long long)b * 512 * TT + (long long)n0 * TT;

    const int wm = (wid >> 2) * 64;
    const int wn = (wid & 3) * 32;
    const int kc = TT / 64;               // 32

    float acc[4][4][4];
    #pragma unroll
    for (int i = 0; i < 4; ++i)
        #pragma unroll
        for (int j = 0; j < 4; ++j)
            #pragma unroll
            for (int q = 0; q < 4; ++q) acc[i][j][q] = 0.f;

    load_stage2(sb,                 tid, tA, tB, TT, TT, 0);   CP_COMMIT();
    load_stage2(sb + AFT_STAGE,     tid, tA, tB, TT, TT, 64);  CP_COMMIT();
    load_stage2(sb + 2 * AFT_STAGE, tid, tA, tB, TT, TT, 128); CP_COMMIT();

    const int rA = (lane & 15);
    const int cA = (lane >> 4);
    const int rB = (lane & 7);
    const int cB = (lane >> 3) & 1;

    for (int k = 0; k < kc; ++k) {
        CP_WAIT2();
        __syncthreads();

        if (k + 3 < kc)
            load_stage2(sb + ((k + 3) & 3) * AFT_STAGE, tid, tA, tB, TT, TT, (k + 3) * 64);
        CP_COMMIT();

        const uint32_t st = sb + (k & 3) * AFT_STAGE;
        const uint32_t aB = st, bB = st + 16384;

        #pragma unroll
        for (int kk = 0; kk < 4; ++kk) {
            uint32_t ah[4][4], bh[4][2];
            #pragma unroll
            for (int i = 0; i < 4; ++i) {
                const int row = wm + i * 16 + rA;
                ldsm_x4(ah[i], aB + row * 128 + (((kk * 2 + cA) ^ (row & 7)) * 16));
            }
            #pragma unroll
            for (int j = 0; j < 4; ++j) {
                const int row = wn + j * 8 + rB;
                ldsm_x2(bh[j], bB + row * 128 + (((kk * 2 + cB) ^ (row & 7)) * 16));
            }
            #pragma unroll
            for (int i = 0; i < 4; ++i)
                #pragma unroll
                for (int j = 0; j < 4; ++j)
                    mma16816(acc[i][j], ah[i], bh[j]);
        }
        __syncthreads();
    }

    // fused epilogue: n even -> num, n+1 -> den
    const int g  = lane >> 2;
    const int tg = lane & 3;
    #pragma unroll
    for (int j = 0; j < 4; ++j) {
        const int n = n0 + wn + j * 8 + tg * 2;     // even
        const int h = n >> 1;
        const float cs0 = cs[b * 512 + n];
        const float cs1 = cs[b * 512 + n + 1];
        #pragma unroll
        for (int i = 0; i < 4; ++i) {
            const int m = m0 + wm + i * 16 + g;
            long long idx = ((long long)(b * TT + m)) * 256 + h;
            float y0 = sigQ[idx] * (acc[i][j][0] + cs0) / (acc[i][j][1] + cs1);
            split2(y0, ythi + idx, ytlo + idx);
            long long idx2 = idx + 8 * 256;
            float y1 = sigQ[idx2] * (acc[i][j][2] + cs0) / (acc[i][j][3] + cs1);
            split2(y1, ythi + idx2, ytlo + idx2);
        }
    }
}

// --------------------------- conversion kernels ----------------------------
__global__ void cvt_split(const float* __restrict__ in,
                          __nv_bfloat16* __restrict__ hi, __nv_bfloat16* __restrict__ lo,
                          int n)
{
    int i = blockIdx.x * blockDim.x + threadIdx.x;
    if (i < n) split2(in[i], hi + i, lo + i);
}

__global__ void cvt_expm1(const float* __restrict__ in, __nv_bfloat16* __restrict__ o, int n)
{
    int i = blockIdx.x * blockDim.x + threadIdx.x;
    if (i < n) o[i] = __float2bfloat16_rn(expm1f(in[i]));
}

__global__ void build_wqkv(const float* __restrict__ Wq, const float* __restrict__ Wk,
                           const float* __restrict__ Wv,
                           const float* __restrict__ bq, const float* __restrict__ bk,
                           const float* __restrict__ bv,
                           __nv_bfloat16* __restrict__ hi, __nv_bfloat16* __restrict__ lo,
                           float* __restrict__ bcat)
{
    int i = blockIdx.x * blockDim.x + threadIdx.x;     // 768*1024
    if (i >= 768 * DIM_) return;
    int n = i / DIM_, k = i % DIM_;
    const float* W = (n < 256) ? Wq : (n < 512) ? Wk : Wv;
    split2(W[(long long)k * 256 + (n & 255)], hi + i, lo + i);
    if (i < 768) {
        const float* b = (i < 256) ? bq : (i < 512) ? bk : bv;
        bcat[i] = b[i & 255];
    }
}

__global__ void build_wpt(const float* __restrict__ Wp,
                          __nv_bfloat16* __restrict__ hi, __nv_bfloat16* __restrict__ lo)
{
    int i = blockIdx.x * blockDim.x + threadIdx.x;     // 1024*256
    if (i >= DIM_ * HID_) return;
    int d = i >> 8, h = i & 255;
    split2(Wp[(long long)h * DIM_ + d], hi + i, lo + i);
}

// sigQ + F (interleaved transposed, bf16) + fp32 colsum partials
__global__ void qkv_post(const float* __restrict__ QKV, float* __restrict__ sigQ,
                         __nv_bfloat16* __restrict__ F, float* __restrict__ cspart)
{
    __shared__ float tkv[32][33], tk[32][33];
    __shared__ float redkv[8][32], redk[8][32];
    const int b = blockIdx.z, sblk = blockIdx.y, s0 = sblk * 32, h0 = blockIdx.x * 32;
    const int tx = threadIdx.x, ty = threadIdx.y;

    #pragma unroll
    for (int r = 0; r < 4; ++r) {
        const int s = s0 + ty + r * 8;
        const float* base = QKV + ((long long)(b * TT + s)) * 768;
        float q  = base[h0 + tx];
        float kk = base[256 + h0 + tx];
        float v  = base[512 + h0 + tx];
        sigQ[((long long)(b * TT + s)) * 256 + h0 + tx] = 1.f / (1.f + expf(-q));
        float ek = expf(kk);
        tkv[ty + r * 8][tx] = ek * v;
        tk [ty + r * 8][tx] = ek;
    }
    __syncthreads();

    // colsum partials over the 32 s-rows (deterministic tree)
    float pkv = 0.f, pk = 0.f;
    #pragma unroll
    for (int r = 0; r < 4; ++r) {
        pkv += tkv[ty + r * 8][tx];
        pk  += tk [ty + r * 8][tx];
    }
    redkv[ty][tx] = pkv;  redk[ty][tx] = pk;
    __syncthreads();
    if (ty == 0) {
        float skv = 0.f, sk = 0.f;
        #pragma unroll
        for (int r = 0; r < 8; ++r) { skv += redkv[r][tx]; sk += redk[r][tx]; }
        const int h = h0 + tx;
        long long o = ((long long)(b * 64 + sblk)) * 512 + 2 * h;
        cspart[o]     = skv;
        cspart[o + 1] = sk;
    }

    // transposed interleaved bf16 write: F[b][2h][s], F[b][2h+1][s]
    #pragma unroll
    for (int r = 0; r < 4; ++r) {
        const int h = h0 + ty + r * 8;
        float v1 = tkv[tx][ty + r * 8];
        float v2 = tk [tx][ty + r * 8];
        long long o1 = ((long long)b * 512 + 2 * h) * TT + s0 + tx;
        F[o1]      = __float2bfloat16_rn(v1);
        F[o1 + TT] = __float2bfloat16_rn(v2);
    }
}

__global__ void cs_reduce(const float* __restrict__ part, float* __restrict__ cs)
{
    int i = blockIdx.x * blockDim.x + threadIdx.x;   // 2048
    if (i >= 4 * 512) return;
    int b = i >> 9, n = i & 511;
    float s = 0.f;
    #pragma unroll 8
    for (int sb = 0; sb < 64; ++sb)
        s += part[(((long long)b * 64 + sb) << 9) + n];
    cs[i] = s;
}

// -------------------------------- launch ------------------------------------
extern "C" void kernel_launch(void* const* d_in, const int* in_sizes, int n_in,
                              void* d_out, int out_size)
{
    const float* x     = (const float*)d_in[0];
    const float* Wq    = (const float*)d_in[1];
    const float* bq    = (const float*)d_in[2];
    const float* Wk    = (const float*)d_in[3];
    const float* bk    = (const float*)d_in[4];
    const float* Wv    = (const float*)d_in[5];
    const float* bv    = (const float*)d_in[6];
    const float* Wp    = (const float*)d_in[7];
    const float* bp    = (const float*)d_in[8];
    const float* wbias = (const float*)d_in[9];
    float* out = (float*)d_out;

    __nv_bfloat16 *pxhi, *pxlo, *pwqh, *pwql, *pR, *pF, *pyth, *pytl, *pwph, *pwpl;
    float *pbq, *pQKV, *psigQ, *pcsp, *pcs;
    cudaGetSymbolAddress((void**)&pxhi, g_xhi);      cudaGetSymbolAddress((void**)&pxlo, g_xlo);
    cudaGetSymbolAddress((void**)&pwqh, g_wqkv_hi);  cudaGetSymbolAddress((void**)&pwql, g_wqkv_lo);
    cudaGetSymbolAddress((void**)&pbq,  g_bqkv);
    cudaGetSymbolAddress((void**)&pR,   g_R);
    cudaGetSymbolAddress((void**)&pQKV, g_QKV);
    cudaGetSymbolAddress((void**)&psigQ, g_sigQ);
    cudaGetSymbolAddress((void**)&pF,   g_F);
    cudaGetSymbolAddress((void**)&pcsp, g_cspart);
    cudaGetSymbolAddress((void**)&pcs,  g_cs);
    cudaGetSymbolAddress((void**)&pyth, g_ythi);     cudaGetSymbolAddress((void**)&pytl, g_ytlo);
    cudaGetSymbolAddress((void**)&pwph, g_wpt_hi);   cudaGetSymbolAddress((void**)&pwpl, g_wpt_lo);

    cudaFuncSetAttribute(gemm_split, cudaFuncAttributeMaxDynamicSharedMemorySize, SPLIT_SMEM);
    cudaFuncSetAttribute(gemm_aft,   cudaFuncAttributeMaxDynamicSharedMemorySize, AFT_SMEM);

    // conversions
    cvt_split<<<(ROWS * DIM_ + 255) / 256, 256>>>(x, pxhi, pxlo, ROWS * DIM_);
    build_wqkv<<<(768 * DIM_ + 255) / 256, 256>>>(Wq, Wk, Wv, bq, bk, bv, pwqh, pwql, pbq);
    cvt_expm1<<<(TT * TT + 255) / 256, 256>>>(wbias, pR, TT * TT);
    build_wpt<<<(DIM_ * HID_ + 255) / 256, 256>>>(Wp, pwph, pwpl);

    // GEMM1: QKV = x @ Wqkv + b
    dim3 g1(768 / 128, ROWS / 128, 1);
    gemm_split<<<g1, 256, SPLIT_SMEM>>>(pxhi, pxlo, pwqh, pwql, pbq, pQKV,
                                        DIM_, DIM_, DIM_, 768);

    // sigQ, F (interleaved), colsum partials -> colsum
    dim3 bq1(32, 8), gq1(HID_ / 32, TT / 32, 4);
    qkv_post<<<gq1, bq1>>>(pQKV, psigQ, pF, pcsp);
    cs_reduce<<<8, 256>>>(pcsp, pcs);

    // GEMM2 + fused AFT epilogue -> Yt (hi/lo)
    dim3 g2(512 / 128, TT / 128, 4);
    gemm_aft<<<g2, 256, AFT_SMEM>>>(pR, pF, pcs, psigQ, pyth, pytl);

    // GEMM3: out = Yt @ Wp + bp
    dim3 g3(DIM_ / 128, ROWS / 128, 1);
    gemm_split<<<g3, 256, SPLIT_SMEM>>>(pyth, pytl, pwph, pwpl, bp, out,
                                        HID_, HID_, HID_, DIM_);
}